// round 12
// baseline (speedup 1.0000x reference)
#include <cuda_runtime.h>
#include <cuda_bf16.h>
#include <math.h>

// ---------------------------------------------------------------------------
// AdaptiveVoxelization
//   coors[N,3]  : zyx voxel index (float/int), -1 if out of range
//   centers[3,R^3], mask[R^3] : adaptive voxel centers (quadratic scaling)
// Output layout (float32 branch): [ coors (N*3) | centers (3*R^3) | mask (R^3) ]
// ---------------------------------------------------------------------------

#define RES   100
#define R3    1000000          // RES^3

// point_cloud_range
#define PCR_X0 (-50.0f)
#define PCR_Y0 (-50.0f)
#define PCR_Z0 ( -1.0f)
#define PCR_X1 (150.0f)
#define PCR_Y1 ( 50.0f)
#define PCR_Z1 (  3.0f)

// voxel size / grid (grid = round((hi-lo)/vs) in f32 == {2000,1000,20})
#define VSX 0.1f
#define VSY 0.1f
#define VSZ 0.2f
#define GX 2000.0f
#define GY 1000.0f
#define GZ   20.0f

#define SCALING 25.0f

// ---------------- kernel 1: dynamic voxelize (float output) ----------------

__device__ __forceinline__ void voxelize_one(float px, float py, float pz,
                                             float& o0, float& o1, float& o2) {
    float fx = floorf(__fdiv_rn(__fsub_rn(px, PCR_X0), VSX));
    float fy = floorf(__fdiv_rn(__fsub_rn(py, PCR_Y0), VSY));
    float fz = floorf(__fdiv_rn(__fsub_rn(pz, PCR_Z0), VSZ));
    bool valid = (fx >= 0.0f) && (fx < GX) &&
                 (fy >= 0.0f) && (fy < GY) &&
                 (fz >= 0.0f) && (fz < GZ);
    o0 = valid ? fz : -1.0f;   // zyx order
    o1 = valid ? fy : -1.0f;
    o2 = valid ? fx : -1.0f;
}

__global__ void voxelize_f4(const float4* __restrict__ pts,
                            float4* __restrict__ out, int nquads) {
    int t = blockIdx.x * blockDim.x + threadIdx.x;
    if (t >= nquads) return;
    float c[12];
#pragma unroll
    for (int r = 0; r < 4; r++) {
        float4 p = pts[4 * t + r];
        voxelize_one(p.x, p.y, p.z, c[3 * r + 0], c[3 * r + 1], c[3 * r + 2]);
    }
    float4* q = out + (size_t)3 * t;
    q[0] = make_float4(c[0], c[1], c[2],  c[3]);
    q[1] = make_float4(c[4], c[5], c[6],  c[7]);
    q[2] = make_float4(c[8], c[9], c[10], c[11]);
}

// scalar tail (only used if N % 4 != 0)
__global__ void voxelize_tail_f(const float* __restrict__ pts,
                                float* __restrict__ out, int start, int npts) {
    int i = start + blockIdx.x * blockDim.x + threadIdx.x;
    if (i >= npts) return;
    float o0, o1, o2;
    voxelize_one(pts[4 * i + 0], pts[4 * i + 1], pts[4 * i + 2], o0, o1, o2);
    out[3 * (size_t)i + 0] = o0;
    out[3 * (size_t)i + 1] = o1;
    out[3 * (size_t)i + 2] = o2;
}

// ---------------- kernel 1b: int32-only output branch ----------------------

__global__ void voxelize_i4(const float4* __restrict__ pts,
                            int4* __restrict__ out, int nquads) {
    int t = blockIdx.x * blockDim.x + threadIdx.x;
    if (t >= nquads) return;
    int c[12];
#pragma unroll
    for (int r = 0; r < 4; r++) {
        float4 p = pts[4 * t + r];
        float o0, o1, o2;
        voxelize_one(p.x, p.y, p.z, o0, o1, o2);
        c[3 * r + 0] = (int)o0; c[3 * r + 1] = (int)o1; c[3 * r + 2] = (int)o2;
    }
    int4* q = out + (size_t)3 * t;
    q[0] = make_int4(c[0], c[1], c[2],  c[3]);
    q[1] = make_int4(c[4], c[5], c[6],  c[7]);
    q[2] = make_int4(c[8], c[9], c[10], c[11]);
}

__global__ void voxelize_tail_i(const float* __restrict__ pts,
                                int* __restrict__ out, int start, int npts) {
    int i = start + blockIdx.x * blockDim.x + threadIdx.x;
    if (i >= npts) return;
    float o0, o1, o2;
    voxelize_one(pts[4 * i + 0], pts[4 * i + 1], pts[4 * i + 2], o0, o1, o2);
    out[3 * (size_t)i + 0] = (int)o0;
    out[3 * (size_t)i + 1] = (int)o1;
    out[3 * (size_t)i + 2] = (int)o2;
}

// ---------------- kernel 2: adaptive voxel centers + mask ------------------

__device__ __forceinline__ float lin_val(float start, float delta, int i) {
    // matches jnp.linspace: start + i * delta, no FMA contraction
    return __fadd_rn(start, __fmul_rn((float)i, delta));
}

__device__ __forceinline__ float norm3(float x, float y, float z) {
    // sqrt((x^2 + y^2) + z^2), IEEE rn
    float s = __fadd_rn(__fadd_rn(__fmul_rn(x, x), __fmul_rn(y, y)),
                        __fmul_rn(z, z));
    return __fsqrt_rn(s);
}

__global__ void centers_kernel(float* __restrict__ centers,
                               float* __restrict__ mask) {
    int idx = blockIdx.x * blockDim.x + threadIdx.x;
    if (idx >= R3) return;

    // linspace deltas (compile-time IEEE rn fold)
    const float dx = (PCR_X1 - PCR_X0) / 99.0f;   // 200/99
    const float dy = (PCR_Y1 - PCR_Y0) / 99.0f;   // 100/99
    const float dz = (PCR_Z1 - PCR_Z0) / 99.0f;   //   4/99

    int i  = idx / (RES * RES);
    int jk = idx - i * (RES * RES);
    int j  = jk / RES;
    int k  = jk - j * RES;

    float x = lin_val(PCR_X0, dx, i);
    float y = lin_val(PCR_Y0, dy, j);
    float z = lin_val(PCR_Z0, dz, k);

    // norm_c = max over grid of sqrt(x^2+y^2+z^2); rounding is monotone, so
    // the max is attained at one of the 8 linspace corners.
    float xe0 = lin_val(PCR_X0, dx, 0),  xe1 = lin_val(PCR_X0, dx, 99);
    float ye0 = lin_val(PCR_Y0, dy, 0),  ye1 = lin_val(PCR_Y0, dy, 99);
    float ze0 = lin_val(PCR_Z0, dz, 0),  ze1 = lin_val(PCR_Z0, dz, 99);
    float nc = 0.0f;
#pragma unroll
    for (int cb = 0; cb < 8; cb++) {
        float cx = (cb & 1) ? xe1 : xe0;
        float cy = (cb & 2) ? ye1 : ye0;
        float cz = (cb & 4) ? ze1 : ze0;
        nc = fmaxf(nc, norm3(cx, cy, cz));
    }

    float nrm   = norm3(x, y, z);
    // quadratic: sf = norm^2 / norm_c^2   (note: norm is sqrt'd then re-squared,
    // matching the reference's |norms|**2)
    float sf    = __fdiv_rn(__fmul_rn(nrm, nrm), __fmul_rn(nc, nc));
    float fac   = __fadd_rn(1.0f, __fmul_rn(sf, SCALING));
    float cxv   = __fmul_rn(x, fac);
    float cyv   = __fmul_rn(y, fac);
    float czv   = __fmul_rn(z, fac);

    bool m = (cxv >= PCR_X0) && (cxv <= PCR_X1) &&
             (cyv >= PCR_Y0) && (cyv <= PCR_Y1) &&
             (czv >= PCR_Z0) && (czv <= PCR_Z1);

    centers[idx]            = cxv;
    centers[R3 + idx]       = cyv;
    centers[2 * R3 + idx]   = czv;
    mask[idx]               = m ? 1.0f : 0.0f;
}

// ---------------------------------------------------------------------------

extern "C" void kernel_launch(void* const* d_in, const int* in_sizes, int n_in,
                              void* d_out, int out_size) {
    const float* pts = (const float*)d_in[0];
    const int npts   = in_sizes[0] / 4;      // [N,4]
    const int nquads = npts / 4;
    const int rem    = npts - nquads * 4;

    const size_t coors_elems = (size_t)npts * 3;

    if ((size_t)out_size >= coors_elems + 4 * (size_t)R3) {
        // float32 concat layout: [coors | centers | mask]
        float* out = (float*)d_out;
        if (nquads > 0)
            voxelize_f4<<<(nquads + 255) / 256, 256>>>(
                (const float4*)pts, (float4*)out, nquads);
        if (rem > 0)
            voxelize_tail_f<<<1, 32>>>(pts, out, nquads * 4, npts);
        float* centers = out + coors_elems;
        float* mask    = centers + 3 * (size_t)R3;
        centers_kernel<<<(R3 + 255) / 256, 256>>>(centers, mask);
    } else {
        // coors-only int32 layout
        int* out = (int*)d_out;
        if (nquads > 0)
            voxelize_i4<<<(nquads + 255) / 256, 256>>>(
                (const float4*)pts, (int4*)out, nquads);
        if (rem > 0)
            voxelize_tail_i<<<1, 32>>>(pts, out, nquads * 4, npts);
    }
}

// round 13
// speedup vs baseline: 1.1737x; 1.1737x over previous
#include <cuda_runtime.h>
#include <cuda_bf16.h>
#include <math.h>

// ---------------------------------------------------------------------------
// AdaptiveVoxelization — fused single-kernel version
//   coors[N,3]  : zyx voxel index, -1 if out of range
//   centers[3,R^3], mask[R^3] : adaptive voxel centers (quadratic scaling)
// Output layout (float32 branch): [ coors (N*3) | centers (3*R^3) | mask (R^3) ]
// Heterogeneous blocks: first CEN_BLOCKS blocks compute centers (L2/compute
// bound), remaining blocks do voxelization (DRAM bound) -> work overlaps.
// ---------------------------------------------------------------------------

#define RES   100
#define R3    1000000          // RES^3
#define CEN_QUADS (R3 / 4)     // 250000 threads, 4 k-consecutive cells each

// point_cloud_range
#define PCR_X0 (-50.0f)
#define PCR_Y0 (-50.0f)
#define PCR_Z0 ( -1.0f)
#define PCR_X1 (150.0f)
#define PCR_Y1 ( 50.0f)
#define PCR_Z1 (  3.0f)

// voxel size / grid (grid = round((hi-lo)/vs) in f32 == {2000,1000,20})
#define VSX 0.1f
#define VSY 0.1f
#define VSZ 0.2f
#define GX 2000.0f
#define GY 1000.0f
#define GZ   20.0f

#define SCALING 25.0f
#define TPB 256

// ---------------- shared device helpers ------------------------------------

__device__ __forceinline__ void voxelize_one(float px, float py, float pz,
                                             float& o0, float& o1, float& o2) {
    // bit-exact vs reference: rn subtract, rn divide, floor
    float fx = floorf(__fdiv_rn(__fsub_rn(px, PCR_X0), VSX));
    float fy = floorf(__fdiv_rn(__fsub_rn(py, PCR_Y0), VSY));
    float fz = floorf(__fdiv_rn(__fsub_rn(pz, PCR_Z0), VSZ));
    bool valid = (fx >= 0.0f) && (fx < GX) &&
                 (fy >= 0.0f) && (fy < GY) &&
                 (fz >= 0.0f) && (fz < GZ);
    o0 = valid ? fz : -1.0f;   // zyx order
    o1 = valid ? fy : -1.0f;
    o2 = valid ? fx : -1.0f;
}

__device__ __forceinline__ float lin_val(float start, float delta, int i) {
    // matches jnp.linspace: start + i * delta, no FMA contraction
    return __fadd_rn(start, __fmul_rn((float)i, delta));
}

__device__ __forceinline__ float norm3(float x, float y, float z) {
    float s = __fadd_rn(__fadd_rn(__fmul_rn(x, x), __fmul_rn(y, y)),
                        __fmul_rn(z, z));
    return __fsqrt_rn(s);
}

// ---------------- fused kernel ---------------------------------------------

__global__ void fused_kernel(const float4* __restrict__ pts,
                             float4* __restrict__ coors,     // N*3 floats
                             float*  __restrict__ centers,   // 3*R3 floats
                             float*  __restrict__ mask,      // R3 floats
                             int nquads, int cenBlocks) {
    int b = blockIdx.x;

    if (b < cenBlocks) {
        // ---- centers role: 4 consecutive k-cells per thread ----
        int t = b * TPB + threadIdx.x;
        if (t >= CEN_QUADS) return;

        const float dx = (PCR_X1 - PCR_X0) / 99.0f;
        const float dy = (PCR_Y1 - PCR_Y0) / 99.0f;
        const float dz = (PCR_Z1 - PCR_Z0) / 99.0f;

        int i  = t / 2500;            // t = i*2500 + j*25 + kq
        int r0 = t - i * 2500;
        int j  = r0 / 25;
        int kq = r0 - j * 25;
        int k4 = kq * 4;

        float x = lin_val(PCR_X0, dx, i);
        float y = lin_val(PCR_Y0, dy, j);

        // norm_c from the 8 linspace corners (monotone rounding -> grid max)
        float xe0 = lin_val(PCR_X0, dx, 0),  xe1 = lin_val(PCR_X0, dx, 99);
        float ye0 = lin_val(PCR_Y0, dy, 0),  ye1 = lin_val(PCR_Y0, dy, 99);
        float ze0 = lin_val(PCR_Z0, dz, 0),  ze1 = lin_val(PCR_Z0, dz, 99);
        float nc = 0.0f;
#pragma unroll
        for (int cb = 0; cb < 8; cb++) {
            float cx = (cb & 1) ? xe1 : xe0;
            float cy = (cb & 2) ? ye1 : ye0;
            float cz = (cb & 4) ? ze1 : ze0;
            nc = fmaxf(nc, norm3(cx, cy, cz));
        }
        float nc2 = __fmul_rn(nc, nc);

        float cx[4], cy[4], cz[4], mk[4];
#pragma unroll
        for (int q = 0; q < 4; q++) {
            float z   = lin_val(PCR_Z0, dz, k4 + q);
            float nrm = norm3(x, y, z);
            float sf  = __fdiv_rn(__fmul_rn(nrm, nrm), nc2);
            float fac = __fadd_rn(1.0f, __fmul_rn(sf, SCALING));
            float vx  = __fmul_rn(x, fac);
            float vy  = __fmul_rn(y, fac);
            float vz  = __fmul_rn(z, fac);
            bool m = (vx >= PCR_X0) && (vx <= PCR_X1) &&
                     (vy >= PCR_Y0) && (vy <= PCR_Y1) &&
                     (vz >= PCR_Z0) && (vz <= PCR_Z1);
            cx[q] = vx; cy[q] = vy; cz[q] = vz; mk[q] = m ? 1.0f : 0.0f;
        }

        int idx4 = t;  // float4 index; base offsets R3, 2*R3 are %4==0
        ((float4*)centers)[idx4]              = make_float4(cx[0], cx[1], cx[2], cx[3]);
        ((float4*)(centers + R3))[idx4]       = make_float4(cy[0], cy[1], cy[2], cy[3]);
        ((float4*)(centers + 2 * R3))[idx4]   = make_float4(cz[0], cz[1], cz[2], cz[3]);
        ((float4*)mask)[idx4]                 = make_float4(mk[0], mk[1], mk[2], mk[3]);
        return;
    }

    // ---- voxelize role: 4 points per thread ----
    int t = (b - cenBlocks) * TPB + threadIdx.x;
    if (t >= nquads) return;
    float c[12];
#pragma unroll
    for (int r = 0; r < 4; r++) {
        float4 p = pts[4 * t + r];
        voxelize_one(p.x, p.y, p.z, c[3 * r + 0], c[3 * r + 1], c[3 * r + 2]);
    }
    float4* q = coors + (size_t)3 * t;
    q[0] = make_float4(c[0], c[1], c[2],  c[3]);
    q[1] = make_float4(c[4], c[5], c[6],  c[7]);
    q[2] = make_float4(c[8], c[9], c[10], c[11]);
}

// ---------------- scalar tail (N % 4 != 0 only) ----------------------------

__global__ void voxelize_tail_f(const float* __restrict__ pts,
                                float* __restrict__ out, int start, int npts) {
    int i = start + blockIdx.x * blockDim.x + threadIdx.x;
    if (i >= npts) return;
    float o0, o1, o2;
    voxelize_one(pts[4 * i + 0], pts[4 * i + 1], pts[4 * i + 2], o0, o1, o2);
    out[3 * (size_t)i + 0] = o0;
    out[3 * (size_t)i + 1] = o1;
    out[3 * (size_t)i + 2] = o2;
}

// ---------------- int32-only fallback branch -------------------------------

__global__ void voxelize_i4(const float4* __restrict__ pts,
                            int4* __restrict__ out, int nquads) {
    int t = blockIdx.x * blockDim.x + threadIdx.x;
    if (t >= nquads) return;
    int c[12];
#pragma unroll
    for (int r = 0; r < 4; r++) {
        float4 p = pts[4 * t + r];
        float o0, o1, o2;
        voxelize_one(p.x, p.y, p.z, o0, o1, o2);
        c[3 * r + 0] = (int)o0; c[3 * r + 1] = (int)o1; c[3 * r + 2] = (int)o2;
    }
    int4* q = out + (size_t)3 * t;
    q[0] = make_int4(c[0], c[1], c[2],  c[3]);
    q[1] = make_int4(c[4], c[5], c[6],  c[7]);
    q[2] = make_int4(c[8], c[9], c[10], c[11]);
}

__global__ void voxelize_tail_i(const float* __restrict__ pts,
                                int* __restrict__ out, int start, int npts) {
    int i = start + blockIdx.x * blockDim.x + threadIdx.x;
    if (i >= npts) return;
    float o0, o1, o2;
    voxelize_one(pts[4 * i + 0], pts[4 * i + 1], pts[4 * i + 2], o0, o1, o2);
    out[3 * (size_t)i + 0] = (int)o0;
    out[3 * (size_t)i + 1] = (int)o1;
    out[3 * (size_t)i + 2] = (int)o2;
}

// ---------------------------------------------------------------------------

extern "C" void kernel_launch(void* const* d_in, const int* in_sizes, int n_in,
                              void* d_out, int out_size) {
    const float* pts = (const float*)d_in[0];
    const int npts   = in_sizes[0] / 4;      // [N,4]
    const int nquads = npts / 4;
    const int rem    = npts - nquads * 4;

    const size_t coors_elems = (size_t)npts * 3;

    if ((size_t)out_size >= coors_elems + 4 * (size_t)R3) {
        // float32 concat layout: [coors | centers | mask]
        float* out     = (float*)d_out;
        float* centers = out + coors_elems;
        float* mask    = centers + 3 * (size_t)R3;

        const int cenBlocks = (CEN_QUADS + TPB - 1) / TPB;   // 977
        const int voxBlocks = (nquads + TPB - 1) / TPB;
        fused_kernel<<<cenBlocks + voxBlocks, TPB>>>(
            (const float4*)pts, (float4*)out, centers, mask, nquads, cenBlocks);
        if (rem > 0)
            voxelize_tail_f<<<1, 32>>>(pts, out, nquads * 4, npts);
    } else {
        // coors-only int32 layout
        int* out = (int*)d_out;
        if (nquads > 0)
            voxelize_i4<<<(nquads + TPB - 1) / TPB, TPB>>>(
                (const float4*)pts, (int4*)out, nquads);
        if (rem > 0)
            voxelize_tail_i<<<1, 32>>>(pts, out, nquads * 4, npts);
    }
}